// round 15
// baseline (speedup 1.0000x reference)
#include <cuda_runtime.h>
#include <cuda_fp16.h>
#include <cstdint>
#include <cstddef>

#define TOK   16384      // B*N tokens
#define DIM   2048
#define NQKV  6144       // Q|K|V output columns
#define BM    128
#define BN    128
#define BK    64         // fp16 elements per K chunk (128 bytes/row)
#define GEMM_THREADS 256
#define STAGE_BYTES 32768            // 16KB A + 16KB B per stage
#define SMEM_BYTES (3 * STAGE_BYTES) // 3-stage pipeline

// k_mid: 8 tokens/block; per token q|k|v each 16 rows x 272B
#define MID_MAT_BYTES 4352           // 16 * 272
#define MID_TOK_BYTES 13056          // 3 * 4352
#define MID_SMEM_BYTES (8 * MID_TOK_BYTES)   // 104448

// ---------------- device scratch (module-load allocated, not runtime) ----------------
__device__ __half g_x[(size_t)TOK * DIM];       // fp16(x)
__device__ __half g_wqkv[(size_t)NQKV * DIM];   // [Wq^T ; Wk^T ; Wv^T] fp16
__device__ __half g_wo[(size_t)DIM * DIM];      // Wo^T fp16
__device__ __half g_qkv[(size_t)TOK * NQKV];    // fp16 Q|K|V
__device__ __half g_o[(size_t)TOK * DIM];       // fp16(o)

// ---------------- PTX helpers ----------------
__device__ __forceinline__ uint32_t smem_u32(const void* p) {
    uint32_t a;
    asm("{ .reg .u64 t; cvta.to.shared.u64 t, %1; cvt.u32.u64 %0, t; }" : "=r"(a) : "l"(p));
    return a;
}
__device__ __forceinline__ void cp_async16(uint32_t d, const void* g) {
    asm volatile("cp.async.cg.shared.global [%0], [%1], 16;" :: "r"(d), "l"(g) : "memory");
}
__device__ __forceinline__ void ldsm_x4(uint32_t* r, uint32_t addr) {
    asm volatile("ldmatrix.sync.aligned.m8n8.x4.shared.b16 {%0,%1,%2,%3}, [%4];"
                 : "=r"(r[0]), "=r"(r[1]), "=r"(r[2]), "=r"(r[3]) : "r"(addr));
}
__device__ __forceinline__ void ldsm_x4_t(uint32_t* r, uint32_t addr) {
    asm volatile("ldmatrix.sync.aligned.m8n8.x4.trans.shared.b16 {%0,%1,%2,%3}, [%4];"
                 : "=r"(r[0]), "=r"(r[1]), "=r"(r[2]), "=r"(r[3]) : "r"(addr));
}
__device__ __forceinline__ void mma16816(float* c, const uint32_t* a, const uint32_t* b) {
    asm volatile(
        "mma.sync.aligned.m16n8k16.row.col.f32.f16.f16.f32 "
        "{%0,%1,%2,%3}, {%4,%5,%6,%7}, {%8,%9}, {%0,%1,%2,%3};"
        : "+f"(c[0]), "+f"(c[1]), "+f"(c[2]), "+f"(c[3])
        : "r"(a[0]), "r"(a[1]), "r"(a[2]), "r"(a[3]), "r"(b[0]), "r"(b[1]));
}
__device__ __forceinline__ uint32_t f2h2(float a, float b) {
    __half2 h = __floats2half2_rn(a, b);
    return *reinterpret_cast<uint32_t*>(&h);
}

// ---------------- kernel 1: fused prep — weight transpose (z<4) + x convert (z==4) ----------------
__global__ void k_prep(const float* __restrict__ x,
                       const float* __restrict__ Wq, const float* __restrict__ Wk,
                       const float* __restrict__ Wv, const float* __restrict__ Wo,
                       __half* __restrict__ xh,
                       __half* __restrict__ wqkv, __half* __restrict__ wo) {
    __shared__ float t[32][33];
    const int z = blockIdx.z;
    const int tx = threadIdx.x, ty = threadIdx.y;
    if (z < 4) {
        const float* W = (z == 0) ? Wq : (z == 1) ? Wk : (z == 2) ? Wv : Wo;
        __half* out = (z < 3) ? wqkv + (size_t)z * DIM * DIM : wo;
        const int bx = blockIdx.x, by = blockIdx.y;
#pragma unroll
        for (int i = 0; i < 32; i += 8)
            t[ty + i][tx] = W[(size_t)(by * 32 + ty + i) * DIM + bx * 32 + tx];
        __syncthreads();
#pragma unroll
        for (int i = 0; i < 32; i += 8) {
            float v = t[tx][ty + i];
            out[(size_t)(bx * 32 + ty + i) * DIM + by * 32 + tx] = __float2half_rn(v);
        }
    } else {
        const int tid = ty * 32 + tx;
        const int base = (blockIdx.y * 64 + blockIdx.x) * 256 + tid;   // 0..1048575
        const float4* s4 = (const float4*)x;
        __half2* hp = (__half2*)xh;
#pragma unroll
        for (int j = 0; j < 8; j++) {
            const int i = base + j * 1048576;
            float4 v = s4[i];
            hp[2 * i]     = __halves2half2(__float2half_rn(v.x), __float2half_rn(v.y));
            hp[2 * i + 1] = __halves2half2(__float2half_rn(v.z), __float2half_rn(v.w));
        }
    }
}

// ---------------- GEMM: issue global->smem loads for one K chunk (256 threads) ----------------
__device__ __forceinline__ void issue_chunk(
    const __half* __restrict__ A, const __half* __restrict__ B,
    int chunk, int m0, int n0, int K, int r0, int c,
    const uint32_t* soff, uint32_t stage_base) {
    const int k0 = chunk * BK;
    const char* ga = (const char*)(A + (size_t)(m0 + r0) * K + k0 + c * 8);
    const char* gb = (const char*)(B + (size_t)(n0 + r0) * K + k0 + c * 8);
    const size_t rs = (size_t)32 * K * sizeof(__half);
    const uint32_t dstA = stage_base, dstB = stage_base + 16384;
#pragma unroll
    for (int j = 0; j < 4; j++) {
        cp_async16(dstA + soff[j], ga + (size_t)j * rs);
        cp_async16(dstB + soff[j], gb + (size_t)j * rs);
    }
    asm volatile("cp.async.commit_group;" ::: "memory");
}

// ---------------- kernel 2/4: fp16 mma.sync GEMM, 128x128 tile, 3-stage (R11 config) ----------------
template <typename CT>
__global__ void __launch_bounds__(GEMM_THREADS, 2)
k_gemm(const __half* __restrict__ A, const __half* __restrict__ B,
       CT* __restrict__ C, int K, int ldc) {
    extern __shared__ char smem[];
    const uint32_t sb = smem_u32(smem);
    const int tid = threadIdx.x, wid = tid >> 5, lane = tid & 31;
    const int m0 = blockIdx.y * BM, n0 = blockIdx.x * BN;
    const int NCH = K / BK;

    const int c = tid & 7, r0 = tid >> 3;
    uint32_t soff[4];
#pragma unroll
    for (int j = 0; j < 4; j++) {
        uint32_t o = (uint32_t)(r0 + 32 * j) * 128u + (uint32_t)c * 16u;
        soff[j] = o ^ ((o >> 3) & 0x70u);
    }

    const int warp_m = (wid >> 1) * 32, warp_n = (wid & 1) * 64;

    const uint32_t xorv = (uint32_t)(lane & 7);
    uint32_t aoff[2];
    const uint32_t adk = (uint32_t)(lane >> 4);
#pragma unroll
    for (int mt = 0; mt < 2; mt++)
        aoff[mt] = (uint32_t)(warp_m + mt * 16 + (lane & 15)) * 128u;
    uint32_t boff[4];
    const uint32_t bdk = (uint32_t)((lane >> 3) & 1);
    {
        const int br = ((lane >> 4) << 3) + (lane & 7);   // 0..15
#pragma unroll
        for (int p = 0; p < 4; p++)
            boff[p] = (uint32_t)(warp_n + p * 16 + br) * 128u;
    }

    float acc[2][8][4];
#pragma unroll
    for (int mt = 0; mt < 2; mt++)
#pragma unroll
        for (int nt = 0; nt < 8; nt++)
#pragma unroll
            for (int e = 0; e < 4; e++) acc[mt][nt][e] = 0.f;

    issue_chunk(A, B, 0, m0, n0, K, r0, c, soff, sb);
    issue_chunk(A, B, 1, m0, n0, K, r0, c, soff, sb + STAGE_BYTES);

    int stage = 0;
    int wstage = 2;
    for (int i = 0; i < NCH; i++) {
        asm volatile("cp.async.wait_group 1;" ::: "memory");
        __syncthreads();
        if (i + 2 < NCH)
            issue_chunk(A, B, i + 2, m0, n0, K, r0, c, soff,
                        sb + (uint32_t)wstage * STAGE_BYTES);
        else
            asm volatile("cp.async.commit_group;" ::: "memory");

        const uint32_t bufA = sb + (uint32_t)stage * STAGE_BYTES;
        const uint32_t bufB = bufA + 16384;
#pragma unroll
        for (int kk = 0; kk < 4; kk++) {
            const uint32_t kc = (uint32_t)kk * 2;
            uint32_t a[2][4];
#pragma unroll
            for (int mt = 0; mt < 2; mt++)
                ldsm_x4(a[mt], bufA + aoff[mt] + (((kc + adk) ^ xorv) << 4));
            uint32_t b[8][2];
#pragma unroll
            for (int p = 0; p < 4; p++) {
                uint32_t r[4];
                ldsm_x4(r, bufB + boff[p] + (((kc + bdk) ^ xorv) << 4));
                b[2 * p][0] = r[0]; b[2 * p][1] = r[1];
                b[2 * p + 1][0] = r[2]; b[2 * p + 1][1] = r[3];
            }
#pragma unroll
            for (int mt = 0; mt < 2; mt++)
#pragma unroll
                for (int nt = 0; nt < 8; nt++)
                    mma16816(acc[mt][nt], a[mt], b[nt]);
        }
        stage = (stage == 2) ? 0 : stage + 1;
        wstage = (wstage == 2) ? 0 : wstage + 1;
    }

    // epilogue: fp32 accumulators -> C (fp32 or fp16)
#pragma unroll
    for (int mt = 0; mt < 2; mt++) {
        const int row = m0 + warp_m + mt * 16 + (lane >> 2);
#pragma unroll
        for (int nt = 0; nt < 8; nt++) {
            const int col = n0 + warp_n + nt * 8 + (lane & 3) * 2;
            if constexpr (sizeof(CT) == 4) {
                float2 v0 = make_float2(acc[mt][nt][0], acc[mt][nt][1]);
                float2 v1 = make_float2(acc[mt][nt][2], acc[mt][nt][3]);
                *(float2*)((float*)C + (size_t)row * ldc + col) = v0;
                *(float2*)((float*)C + (size_t)(row + 8) * ldc + col) = v1;
            } else {
                __half2 v0 = __floats2half2_rn(acc[mt][nt][0], acc[mt][nt][1]);
                __half2 v1 = __floats2half2_rn(acc[mt][nt][2], acc[mt][nt][3]);
                *(__half2*)((__half*)C + (size_t)row * ldc + col) = v0;
                *(__half2*)((__half*)C + (size_t)(row + 8) * ldc + col) = v1;
            }
        }
    }
}

// ---------------- kernel 3: per-token (Q K^T) V via tensor cores ----------------
// 8 tokens/block, 1 warp per token, warp-local cp.async pipeline (R11 config).
__global__ void __launch_bounds__(256, 2) k_mid(const __half* __restrict__ qkv,
                                                __half* __restrict__ o) {
    extern __shared__ char sm[];
    const uint32_t sb = smem_u32(sm);
    const int tid = threadIdx.x, wid = tid >> 5, lane = tid & 31;
    const int t0 = blockIdx.x * 8;

    const char* row = (const char*)(qkv + (size_t)(t0 + wid) * NQKV);
    const uint32_t tb = sb + (uint32_t)wid * MID_TOK_BYTES;

    // group 1: Q + K
#pragma unroll
    for (int i = 0; i < 16; i++) {
        const int l8 = lane + 32 * i;
        const int idx = l8 * 8;
        const int mat = idx >> 11;
        const int m = idx & 2047;
        cp_async16(tb + mat * MID_MAT_BYTES + (m >> 7) * 272 + (m & 127) * 2,
                   row + (size_t)l8 * 16);
    }
    asm volatile("cp.async.commit_group;" ::: "memory");
    // group 2: V
#pragma unroll
    for (int i = 16; i < 24; i++) {
        const int l8 = lane + 32 * i;
        const int idx = l8 * 8;
        const int m = idx & 2047;
        cp_async16(tb + 2 * MID_MAT_BYTES + (m >> 7) * 272 + (m & 127) * 2,
                   row + (size_t)l8 * 16);
    }
    asm volatile("cp.async.commit_group;" ::: "memory");

    const uint32_t qb = tb, kb = tb + MID_MAT_BYTES, vb = tb + 2 * MID_MAT_BYTES;

    asm volatile("cp.async.wait_group 1;" ::: "memory");
    __syncwarp();

    // ---- S = Q @ K^T (m16 n16 k128) ----
    float s0[4] = {0.f, 0.f, 0.f, 0.f}, s1[4] = {0.f, 0.f, 0.f, 0.f};
    const uint32_t qaddr = qb + (uint32_t)(lane & 15) * 272u + (uint32_t)(lane >> 4) * 16u;
    const uint32_t kaddr = kb + (uint32_t)(((lane >> 4) << 3) + (lane & 7)) * 272u
                              + (uint32_t)((lane >> 3) & 1) * 16u;
#pragma unroll
    for (int kk = 0; kk < 8; kk++) {
        uint32_t a[4], b[4];
        ldsm_x4(a, qaddr + kk * 32);
        ldsm_x4(b, kaddr + kk * 32);
        mma16816(s0, a, b);
        mma16816(s1, a, b + 2);
    }

    uint32_t sa[4];
    sa[0] = f2h2(s0[0], s0[1]);
    sa[1] = f2h2(s0[2], s0[3]);
    sa[2] = f2h2(s1[0], s1[1]);
    sa[3] = f2h2(s1[2], s1[3]);

    asm volatile("cp.async.wait_group 0;" ::: "memory");
    __syncwarp();

    // ---- O = S @ V (m16 n128 k16) ----
    const uint32_t vaddr = vb + (uint32_t)(lane & 15) * 272u + (uint32_t)(lane >> 4) * 16u;
    __half* op = o + (size_t)(t0 + wid) * DIM;
    const int orow = lane >> 2;
    const int colp = (lane & 3) * 2;
#pragma unroll
    for (int p = 0; p < 8; p++) {
        uint32_t v[4];
        ldsm_x4_t(v, vaddr + p * 32);
        float o0[4] = {0.f, 0.f, 0.f, 0.f}, o1[4] = {0.f, 0.f, 0.f, 0.f};
        mma16816(o0, sa, v);
        mma16816(o1, sa, v + 2);
        __half2 h00, h01, h10, h11;
        h00 = __floats2half2_rn(o0[0], o0[1]);
        h01 = __floats2half2_rn(o0[2], o0[3]);
        h10 = __floats2half2_rn(o1[0], o1[1]);
        h11 = __floats2half2_rn(o1[2], o1[3]);
        *(__half2*)(op + orow * 128 + p * 16 + colp) = h00;
        *(__half2*)(op + (orow + 8) * 128 + p * 16 + colp) = h01;
        *(__half2*)(op + orow * 128 + p * 16 + 8 + colp) = h10;
        *(__half2*)(op + (orow + 8) * 128 + p * 16 + 8 + colp) = h11;
    }
}

// ---------------- static-init preload ----------------
namespace {
struct Preload {
    Preload() {
        void* p = nullptr;
        cudaGetSymbolAddress(&p, g_x);
        cudaFuncAttributes a;
        cudaFuncGetAttributes(&a, k_prep);
        cudaFuncGetAttributes(&a, k_gemm<float>);
        cudaFuncGetAttributes(&a, k_gemm<__half>);
        cudaFuncGetAttributes(&a, k_mid);
        cudaFuncSetAttribute(k_gemm<float>, cudaFuncAttributeMaxDynamicSharedMemorySize, SMEM_BYTES);
        cudaFuncSetAttribute(k_gemm<__half>, cudaFuncAttributeMaxDynamicSharedMemorySize, SMEM_BYTES);
        cudaFuncSetAttribute(k_mid, cudaFuncAttributeMaxDynamicSharedMemorySize, MID_SMEM_BYTES);
    }
};
Preload preload_instance;
}  // namespace

// ---------------- launch ----------------
extern "C" void kernel_launch(void* const* d_in, const int* in_sizes, int n_in,
                              void* d_out, int out_size) {
    const float* x  = (const float*)d_in[0];
    const float* Wq = (const float*)d_in[1];
    const float* Wk = (const float*)d_in[2];
    const float* Wv = (const float*)d_in[3];
    const float* Wo = (const float*)d_in[4];
    float* out = (float*)d_out;

    __half *xh, *wqkv, *wo, *qkv, *oh;
    cudaGetSymbolAddress((void**)&xh,   g_x);
    cudaGetSymbolAddress((void**)&wqkv, g_wqkv);
    cudaGetSymbolAddress((void**)&wo,   g_wo);
    cudaGetSymbolAddress((void**)&qkv,  g_qkv);
    cudaGetSymbolAddress((void**)&oh,   g_o);

    cudaFuncSetAttribute(k_gemm<float>, cudaFuncAttributeMaxDynamicSharedMemorySize, SMEM_BYTES);
    cudaFuncSetAttribute(k_gemm<__half>, cudaFuncAttributeMaxDynamicSharedMemorySize, SMEM_BYTES);
    cudaFuncSetAttribute(k_mid, cudaFuncAttributeMaxDynamicSharedMemorySize, MID_SMEM_BYTES);

    // 1) fused prep: weight transpose+round (z<4) and x convert (z=4), one launch
    k_prep<<<dim3(64, 64, 5), dim3(32, 8)>>>(x, Wq, Wk, Wv, Wo, xh, wqkv, wo);
    // 2) QKV = x @ [Wq|Wk|Wv]   (fp16 in, fp16 out)
    k_gemm<__half><<<dim3(NQKV / BN, TOK / BM), GEMM_THREADS, SMEM_BYTES>>>(
        xh, wqkv, qkv, DIM, NQKV);
    // 3) per-token (QK^T)V via tensor cores, 8 tokens/block, warp-local pipeline
    k_mid<<<TOK / 8, 256, MID_SMEM_BYTES>>>(qkv, oh);
    // 4) out = o @ Wo  (fp32 out)
    k_gemm<float><<<dim3(DIM / BN, TOK / BM), GEMM_THREADS, SMEM_BYTES>>>(
        oh, wo, out, DIM, DIM);
}

// round 16
// speedup vs baseline: 1.5216x; 1.5216x over previous
#include <cuda_runtime.h>
#include <cuda_fp16.h>
#include <cstdint>
#include <cstddef>

#define TOK   16384      // B*N tokens
#define DIM   2048
#define NQKV  6144       // Q|K|V output columns
#define BM    128
#define BN    128
#define BK    64         // fp16 elements per K chunk (128 bytes/row)
#define GEMM_THREADS 256
#define STAGE_BYTES 32768            // 16KB A + 16KB B per stage
#define SMEM_BYTES (3 * STAGE_BYTES) // 3-stage pipeline

// k_mid: 8 tokens/block; per token q|k|v each 16 rows x 272B
#define MID_MAT_BYTES 4352           // 16 * 272
#define MID_TOK_BYTES 13056          // 3 * 4352
#define MID_SMEM_BYTES (8 * MID_TOK_BYTES)   // 104448

// ---------------- device scratch (module-load allocated, not runtime) ----------------
__device__ __half g_x[(size_t)TOK * DIM];       // fp16(x)
__device__ __half g_wqkv[(size_t)NQKV * DIM];   // [Wq^T ; Wk^T ; Wv^T] fp16
__device__ __half g_wo[(size_t)DIM * DIM];      // Wo^T fp16
__device__ __half g_qkv[(size_t)TOK * NQKV];    // fp16 Q|K|V
__device__ __half g_o[(size_t)TOK * DIM];       // fp16(o)

// ---------------- PTX helpers ----------------
__device__ __forceinline__ uint32_t smem_u32(const void* p) {
    uint32_t a;
    asm("{ .reg .u64 t; cvta.to.shared.u64 t, %1; cvt.u32.u64 %0, t; }" : "=r"(a) : "l"(p));
    return a;
}
__device__ __forceinline__ void cp_async16(uint32_t d, const void* g) {
    asm volatile("cp.async.cg.shared.global [%0], [%1], 16;" :: "r"(d), "l"(g) : "memory");
}
__device__ __forceinline__ void ldsm_x4(uint32_t* r, uint32_t addr) {
    asm volatile("ldmatrix.sync.aligned.m8n8.x4.shared.b16 {%0,%1,%2,%3}, [%4];"
                 : "=r"(r[0]), "=r"(r[1]), "=r"(r[2]), "=r"(r[3]) : "r"(addr));
}
__device__ __forceinline__ void ldsm_x4_t(uint32_t* r, uint32_t addr) {
    asm volatile("ldmatrix.sync.aligned.m8n8.x4.trans.shared.b16 {%0,%1,%2,%3}, [%4];"
                 : "=r"(r[0]), "=r"(r[1]), "=r"(r[2]), "=r"(r[3]) : "r"(addr));
}
__device__ __forceinline__ void mma16816(float* c, const uint32_t* a, const uint32_t* b) {
    asm volatile(
        "mma.sync.aligned.m16n8k16.row.col.f32.f16.f16.f32 "
        "{%0,%1,%2,%3}, {%4,%5,%6,%7}, {%8,%9}, {%0,%1,%2,%3};"
        : "+f"(c[0]), "+f"(c[1]), "+f"(c[2]), "+f"(c[3])
        : "r"(a[0]), "r"(a[1]), "r"(a[2]), "r"(a[3]), "r"(b[0]), "r"(b[1]));
}
__device__ __forceinline__ uint32_t f2h2(float a, float b) {
    __half2 h = __floats2half2_rn(a, b);
    return *reinterpret_cast<uint32_t*>(&h);
}

// ---------------- kernel 1: fused prep — weight transpose (z<4) + x convert (z==4) ----------------
__global__ void k_prep(const float* __restrict__ x,
                       const float* __restrict__ Wq, const float* __restrict__ Wk,
                       const float* __restrict__ Wv, const float* __restrict__ Wo,
                       __half* __restrict__ xh,
                       __half* __restrict__ wqkv, __half* __restrict__ wo) {
    __shared__ float t[32][33];
    const int z = blockIdx.z;
    const int tx = threadIdx.x, ty = threadIdx.y;
    if (z < 4) {
        const float* W = (z == 0) ? Wq : (z == 1) ? Wk : (z == 2) ? Wv : Wo;
        __half* out = (z < 3) ? wqkv + (size_t)z * DIM * DIM : wo;
        const int bx = blockIdx.x, by = blockIdx.y;
#pragma unroll
        for (int i = 0; i < 32; i += 8)
            t[ty + i][tx] = W[(size_t)(by * 32 + ty + i) * DIM + bx * 32 + tx];
        __syncthreads();
#pragma unroll
        for (int i = 0; i < 32; i += 8) {
            float v = t[tx][ty + i];
            out[(size_t)(bx * 32 + ty + i) * DIM + by * 32 + tx] = __float2half_rn(v);
        }
    } else {
        const int tid = ty * 32 + tx;
        const int base = (blockIdx.y * 64 + blockIdx.x) * 256 + tid;   // 0..1048575
        const float4* s4 = (const float4*)x;
        __half2* hp = (__half2*)xh;
#pragma unroll
        for (int j = 0; j < 8; j++) {
            const int i = base + j * 1048576;
            float4 v = s4[i];
            hp[2 * i]     = __halves2half2(__float2half_rn(v.x), __float2half_rn(v.y));
            hp[2 * i + 1] = __halves2half2(__float2half_rn(v.z), __float2half_rn(v.w));
        }
    }
}

// ---------------- GEMM: issue global->smem loads for one K chunk (256 threads) ----------------
__device__ __forceinline__ void issue_chunk(
    const __half* __restrict__ A, const __half* __restrict__ B,
    int chunk, int m0, int n0, int K, int r0, int c,
    const uint32_t* soff, uint32_t stage_base) {
    const int k0 = chunk * BK;
    const char* ga = (const char*)(A + (size_t)(m0 + r0) * K + k0 + c * 8);
    const char* gb = (const char*)(B + (size_t)(n0 + r0) * K + k0 + c * 8);
    const size_t rs = (size_t)32 * K * sizeof(__half);
    const uint32_t dstA = stage_base, dstB = stage_base + 16384;
#pragma unroll
    for (int j = 0; j < 4; j++) {
        cp_async16(dstA + soff[j], ga + (size_t)j * rs);
        cp_async16(dstB + soff[j], gb + (size_t)j * rs);
    }
    asm volatile("cp.async.commit_group;" ::: "memory");
}

// ---------------- kernel 2/4: fp16 mma.sync GEMM, 128x128 tile, 3-stage (R11 config) ----------------
template <typename CT>
__global__ void __launch_bounds__(GEMM_THREADS, 2)
k_gemm(const __half* __restrict__ A, const __half* __restrict__ B,
       CT* __restrict__ C, int K, int ldc) {
    extern __shared__ char smem[];
    const uint32_t sb = smem_u32(smem);
    const int tid = threadIdx.x, wid = tid >> 5, lane = tid & 31;
    const int m0 = blockIdx.y * BM, n0 = blockIdx.x * BN;
    const int NCH = K / BK;

    const int c = tid & 7, r0 = tid >> 3;
    uint32_t soff[4];
#pragma unroll
    for (int j = 0; j < 4; j++) {
        uint32_t o = (uint32_t)(r0 + 32 * j) * 128u + (uint32_t)c * 16u;
        soff[j] = o ^ ((o >> 3) & 0x70u);
    }

    const int warp_m = (wid >> 1) * 32, warp_n = (wid & 1) * 64;

    const uint32_t xorv = (uint32_t)(lane & 7);
    uint32_t aoff[2];
    const uint32_t adk = (uint32_t)(lane >> 4);
#pragma unroll
    for (int mt = 0; mt < 2; mt++)
        aoff[mt] = (uint32_t)(warp_m + mt * 16 + (lane & 15)) * 128u;
    uint32_t boff[4];
    const uint32_t bdk = (uint32_t)((lane >> 3) & 1);
    {
        const int br = ((lane >> 4) << 3) + (lane & 7);   // 0..15
#pragma unroll
        for (int p = 0; p < 4; p++)
            boff[p] = (uint32_t)(warp_n + p * 16 + br) * 128u;
    }

    float acc[2][8][4];
#pragma unroll
    for (int mt = 0; mt < 2; mt++)
#pragma unroll
        for (int nt = 0; nt < 8; nt++)
#pragma unroll
            for (int e = 0; e < 4; e++) acc[mt][nt][e] = 0.f;

    issue_chunk(A, B, 0, m0, n0, K, r0, c, soff, sb);
    issue_chunk(A, B, 1, m0, n0, K, r0, c, soff, sb + STAGE_BYTES);

    int stage = 0;
    int wstage = 2;
    for (int i = 0; i < NCH; i++) {
        asm volatile("cp.async.wait_group 1;" ::: "memory");
        __syncthreads();
        if (i + 2 < NCH)
            issue_chunk(A, B, i + 2, m0, n0, K, r0, c, soff,
                        sb + (uint32_t)wstage * STAGE_BYTES);
        else
            asm volatile("cp.async.commit_group;" ::: "memory");

        const uint32_t bufA = sb + (uint32_t)stage * STAGE_BYTES;
        const uint32_t bufB = bufA + 16384;
#pragma unroll
        for (int kk = 0; kk < 4; kk++) {
            const uint32_t kc = (uint32_t)kk * 2;
            uint32_t a[2][4];
#pragma unroll
            for (int mt = 0; mt < 2; mt++)
                ldsm_x4(a[mt], bufA + aoff[mt] + (((kc + adk) ^ xorv) << 4));
            uint32_t b[8][2];
#pragma unroll
            for (int p = 0; p < 4; p++) {
                uint32_t r[4];
                ldsm_x4(r, bufB + boff[p] + (((kc + bdk) ^ xorv) << 4));
                b[2 * p][0] = r[0]; b[2 * p][1] = r[1];
                b[2 * p + 1][0] = r[2]; b[2 * p + 1][1] = r[3];
            }
#pragma unroll
            for (int mt = 0; mt < 2; mt++)
#pragma unroll
                for (int nt = 0; nt < 8; nt++)
                    mma16816(acc[mt][nt], a[mt], b[nt]);
        }
        stage = (stage == 2) ? 0 : stage + 1;
        wstage = (wstage == 2) ? 0 : wstage + 1;
    }

    // epilogue: fp32 accumulators -> C (fp32 or fp16)
#pragma unroll
    for (int mt = 0; mt < 2; mt++) {
        const int row = m0 + warp_m + mt * 16 + (lane >> 2);
#pragma unroll
        for (int nt = 0; nt < 8; nt++) {
            const int col = n0 + warp_n + nt * 8 + (lane & 3) * 2;
            if constexpr (sizeof(CT) == 4) {
                float2 v0 = make_float2(acc[mt][nt][0], acc[mt][nt][1]);
                float2 v1 = make_float2(acc[mt][nt][2], acc[mt][nt][3]);
                *(float2*)((float*)C + (size_t)row * ldc + col) = v0;
                *(float2*)((float*)C + (size_t)(row + 8) * ldc + col) = v1;
            } else {
                __half2 v0 = __floats2half2_rn(acc[mt][nt][0], acc[mt][nt][1]);
                __half2 v1 = __floats2half2_rn(acc[mt][nt][2], acc[mt][nt][3]);
                *(__half2*)((__half*)C + (size_t)row * ldc + col) = v0;
                *(__half2*)((__half*)C + (size_t)(row + 8) * ldc + col) = v1;
            }
        }
    }
}

// ---------------- kernel 3: per-token (Q K^T) V via tensor cores ----------------
// 8 tokens/block, 1 warp per token, warp-local cp.async pipeline (R11 config).
__global__ void __launch_bounds__(256, 2) k_mid(const __half* __restrict__ qkv,
                                                __half* __restrict__ o) {
    extern __shared__ char sm[];
    const uint32_t sb = smem_u32(sm);
    const int tid = threadIdx.x, wid = tid >> 5, lane = tid & 31;
    const int t0 = blockIdx.x * 8;

    const char* row = (const char*)(qkv + (size_t)(t0 + wid) * NQKV);
    const uint32_t tb = sb + (uint32_t)wid * MID_TOK_BYTES;

    // group 1: Q + K
#pragma unroll
    for (int i = 0; i < 16; i++) {
        const int l8 = lane + 32 * i;
        const int idx = l8 * 8;
        const int mat = idx >> 11;
        const int m = idx & 2047;
        cp_async16(tb + mat * MID_MAT_BYTES + (m >> 7) * 272 + (m & 127) * 2,
                   row + (size_t)l8 * 16);
    }
    asm volatile("cp.async.commit_group;" ::: "memory");
    // group 2: V
#pragma unroll
    for (int i = 16; i < 24; i++) {
        const int l8 = lane + 32 * i;
        const int idx = l8 * 8;
        const int m = idx & 2047;
        cp_async16(tb + 2 * MID_MAT_BYTES + (m >> 7) * 272 + (m & 127) * 2,
                   row + (size_t)l8 * 16);
    }
    asm volatile("cp.async.commit_group;" ::: "memory");

    const uint32_t qb = tb, kb = tb + MID_MAT_BYTES, vb = tb + 2 * MID_MAT_BYTES;

    asm volatile("cp.async.wait_group 1;" ::: "memory");
    __syncwarp();

    // ---- S = Q @ K^T (m16 n16 k128) ----
    float s0[4] = {0.f, 0.f, 0.f, 0.f}, s1[4] = {0.f, 0.f, 0.f, 0.f};
    const uint32_t qaddr = qb + (uint32_t)(lane & 15) * 272u + (uint32_t)(lane >> 4) * 16u;
    const uint32_t kaddr = kb + (uint32_t)(((lane >> 4) << 3) + (lane & 7)) * 272u
                              + (uint32_t)((lane >> 3) & 1) * 16u;
#pragma unroll
    for (int kk = 0; kk < 8; kk++) {
        uint32_t a[4], b[4];
        ldsm_x4(a, qaddr + kk * 32);
        ldsm_x4(b, kaddr + kk * 32);
        mma16816(s0, a, b);
        mma16816(s1, a, b + 2);
    }

    uint32_t sa[4];
    sa[0] = f2h2(s0[0], s0[1]);
    sa[1] = f2h2(s0[2], s0[3]);
    sa[2] = f2h2(s1[0], s1[1]);
    sa[3] = f2h2(s1[2], s1[3]);

    asm volatile("cp.async.wait_group 0;" ::: "memory");
    __syncwarp();

    // ---- O = S @ V (m16 n128 k16) ----
    const uint32_t vaddr = vb + (uint32_t)(lane & 15) * 272u + (uint32_t)(lane >> 4) * 16u;
    __half* op = o + (size_t)(t0 + wid) * DIM;
    const int orow = lane >> 2;
    const int colp = (lane & 3) * 2;
#pragma unroll
    for (int p = 0; p < 8; p++) {
        uint32_t v[4];
        ldsm_x4_t(v, vaddr + p * 32);
        float o0[4] = {0.f, 0.f, 0.f, 0.f}, o1[4] = {0.f, 0.f, 0.f, 0.f};
        mma16816(o0, sa, v);
        mma16816(o1, sa, v + 2);
        __half2 h00, h01, h10, h11;
        h00 = __floats2half2_rn(o0[0], o0[1]);
        h01 = __floats2half2_rn(o0[2], o0[3]);
        h10 = __floats2half2_rn(o1[0], o1[1]);
        h11 = __floats2half2_rn(o1[2], o1[3]);
        *(__half2*)(op + orow * 128 + p * 16 + colp) = h00;
        *(__half2*)(op + (orow + 8) * 128 + p * 16 + colp) = h01;
        *(__half2*)(op + orow * 128 + p * 16 + 8 + colp) = h10;
        *(__half2*)(op + (orow + 8) * 128 + p * 16 + 8 + colp) = h11;
    }
}

// ---------------- static-init preload ----------------
namespace {
struct Preload {
    Preload() {
        void* p = nullptr;
        cudaGetSymbolAddress(&p, g_x);
        cudaFuncAttributes a;
        cudaFuncGetAttributes(&a, k_prep);
        cudaFuncGetAttributes(&a, k_gemm<float>);
        cudaFuncGetAttributes(&a, k_gemm<__half>);
        cudaFuncGetAttributes(&a, k_mid);
        cudaFuncSetAttribute(k_gemm<float>, cudaFuncAttributeMaxDynamicSharedMemorySize, SMEM_BYTES);
        cudaFuncSetAttribute(k_gemm<__half>, cudaFuncAttributeMaxDynamicSharedMemorySize, SMEM_BYTES);
        cudaFuncSetAttribute(k_mid, cudaFuncAttributeMaxDynamicSharedMemorySize, MID_SMEM_BYTES);
    }
};
Preload preload_instance;
}  // namespace

// ---------------- launch ----------------
extern "C" void kernel_launch(void* const* d_in, const int* in_sizes, int n_in,
                              void* d_out, int out_size) {
    const float* x  = (const float*)d_in[0];
    const float* Wq = (const float*)d_in[1];
    const float* Wk = (const float*)d_in[2];
    const float* Wv = (const float*)d_in[3];
    const float* Wo = (const float*)d_in[4];
    float* out = (float*)d_out;

    __half *xh, *wqkv, *wo, *qkv, *oh;
    cudaGetSymbolAddress((void**)&xh,   g_x);
    cudaGetSymbolAddress((void**)&wqkv, g_wqkv);
    cudaGetSymbolAddress((void**)&wo,   g_wo);
    cudaGetSymbolAddress((void**)&qkv,  g_qkv);
    cudaGetSymbolAddress((void**)&oh,   g_o);

    cudaFuncSetAttribute(k_gemm<float>, cudaFuncAttributeMaxDynamicSharedMemorySize, SMEM_BYTES);
    cudaFuncSetAttribute(k_gemm<__half>, cudaFuncAttributeMaxDynamicSharedMemorySize, SMEM_BYTES);
    cudaFuncSetAttribute(k_mid, cudaFuncAttributeMaxDynamicSharedMemorySize, MID_SMEM_BYTES);

    // 1) fused prep: weight transpose+round (z<4) and x convert (z=4), one launch
    k_prep<<<dim3(64, 64, 5), dim3(32, 8)>>>(x, Wq, Wk, Wv, Wo, xh, wqkv, wo);
    // 2) QKV = x @ [Wq|Wk|Wv]   (fp16 in, fp16 out)
    k_gemm<__half><<<dim3(NQKV / BN, TOK / BM), GEMM_THREADS, SMEM_BYTES>>>(
        xh, wqkv, qkv, DIM, NQKV);
    // 3) per-token (QK^T)V via tensor cores, 8 tokens/block, warp-local pipeline
    k_mid<<<TOK / 8, 256, MID_SMEM_BYTES>>>(qkv, oh);
    // 4) out = o @ Wo  (fp32 out)
    k_gemm<float><<<dim3(DIM / BN, TOK / BM), GEMM_THREADS, SMEM_BYTES>>>(
        oh, wo, out, DIM, DIM);
}

// round 17
// speedup vs baseline: 1.5232x; 1.0010x over previous
#include <cuda_runtime.h>
#include <cuda_fp16.h>
#include <cstdint>
#include <cstddef>

#define TOK   16384      // B*N tokens
#define DIM   2048
#define NQKV  6144       // Q|K|V output columns
#define BM    128
#define BN    128
#define BK    64         // fp16 elements per K chunk (128 bytes/row)
#define GEMM_THREADS 256
#define STAGE_BYTES 32768            // 16KB A + 16KB B per stage
#define SMEM_BYTES (3 * STAGE_BYTES) // 3-stage pipeline

// k_mid: 4 tokens/block; per token q|k|v each 16 rows x 272B
#define MID_MAT_BYTES 4352           // 16 * 272
#define MID_TOK_BYTES 13056          // 3 * 4352
#define MID_TPB 4                    // tokens per block
#define MID_SMEM_BYTES (MID_TPB * MID_TOK_BYTES)   // 52224

// ---------------- device scratch (module-load allocated, not runtime) ----------------
__device__ __half g_x[(size_t)TOK * DIM];       // fp16(x)
__device__ __half g_wqkv[(size_t)NQKV * DIM];   // [Wq^T ; Wk^T ; Wv^T] fp16
__device__ __half g_wo[(size_t)DIM * DIM];      // Wo^T fp16
__device__ __half g_qkv[(size_t)TOK * NQKV];    // fp16 Q|K|V
__device__ __half g_o[(size_t)TOK * DIM];       // fp16(o)

// ---------------- PTX helpers ----------------
__device__ __forceinline__ uint32_t smem_u32(const void* p) {
    uint32_t a;
    asm("{ .reg .u64 t; cvta.to.shared.u64 t, %1; cvt.u32.u64 %0, t; }" : "=r"(a) : "l"(p));
    return a;
}
__device__ __forceinline__ void cp_async16(uint32_t d, const void* g) {
    asm volatile("cp.async.cg.shared.global [%0], [%1], 16;" :: "r"(d), "l"(g) : "memory");
}
__device__ __forceinline__ void ldsm_x4(uint32_t* r, uint32_t addr) {
    asm volatile("ldmatrix.sync.aligned.m8n8.x4.shared.b16 {%0,%1,%2,%3}, [%4];"
                 : "=r"(r[0]), "=r"(r[1]), "=r"(r[2]), "=r"(r[3]) : "r"(addr));
}
__device__ __forceinline__ void ldsm_x4_t(uint32_t* r, uint32_t addr) {
    asm volatile("ldmatrix.sync.aligned.m8n8.x4.trans.shared.b16 {%0,%1,%2,%3}, [%4];"
                 : "=r"(r[0]), "=r"(r[1]), "=r"(r[2]), "=r"(r[3]) : "r"(addr));
}
__device__ __forceinline__ void mma16816(float* c, const uint32_t* a, const uint32_t* b) {
    asm volatile(
        "mma.sync.aligned.m16n8k16.row.col.f32.f16.f16.f32 "
        "{%0,%1,%2,%3}, {%4,%5,%6,%7}, {%8,%9}, {%0,%1,%2,%3};"
        : "+f"(c[0]), "+f"(c[1]), "+f"(c[2]), "+f"(c[3])
        : "r"(a[0]), "r"(a[1]), "r"(a[2]), "r"(a[3]), "r"(b[0]), "r"(b[1]));
}
__device__ __forceinline__ uint32_t f2h2(float a, float b) {
    __half2 h = __floats2half2_rn(a, b);
    return *reinterpret_cast<uint32_t*>(&h);
}

// ---------------- kernel 1: fused prep — weight transpose (z<4) + x convert (z==4) ----------------
__global__ void k_prep(const float* __restrict__ x,
                       const float* __restrict__ Wq, const float* __restrict__ Wk,
                       const float* __restrict__ Wv, const float* __restrict__ Wo,
                       __half* __restrict__ xh,
                       __half* __restrict__ wqkv, __half* __restrict__ wo) {
    __shared__ float t[32][33];
    const int z = blockIdx.z;
    const int tx = threadIdx.x, ty = threadIdx.y;
    if (z < 4) {
        const float* W = (z == 0) ? Wq : (z == 1) ? Wk : (z == 2) ? Wv : Wo;
        __half* out = (z < 3) ? wqkv + (size_t)z * DIM * DIM : wo;
        const int bx = blockIdx.x, by = blockIdx.y;
#pragma unroll
        for (int i = 0; i < 32; i += 8)
            t[ty + i][tx] = W[(size_t)(by * 32 + ty + i) * DIM + bx * 32 + tx];
        __syncthreads();
#pragma unroll
        for (int i = 0; i < 32; i += 8) {
            float v = t[tx][ty + i];
            out[(size_t)(bx * 32 + ty + i) * DIM + by * 32 + tx] = __float2half_rn(v);
        }
    } else {
        const int tid = ty * 32 + tx;
        const int base = (blockIdx.y * 64 + blockIdx.x) * 256 + tid;   // 0..1048575
        const float4* s4 = (const float4*)x;
        __half2* hp = (__half2*)xh;
#pragma unroll
        for (int j = 0; j < 8; j++) {
            const int i = base + j * 1048576;
            float4 v = s4[i];
            hp[2 * i]     = __halves2half2(__float2half_rn(v.x), __float2half_rn(v.y));
            hp[2 * i + 1] = __halves2half2(__float2half_rn(v.z), __float2half_rn(v.w));
        }
    }
}

// ---------------- GEMM: issue global->smem loads for one K chunk (256 threads) ----------------
__device__ __forceinline__ void issue_chunk(
    const __half* __restrict__ A, const __half* __restrict__ B,
    int chunk, int m0, int n0, int K, int r0, int c,
    const uint32_t* soff, uint32_t stage_base) {
    const int k0 = chunk * BK;
    const char* ga = (const char*)(A + (size_t)(m0 + r0) * K + k0 + c * 8);
    const char* gb = (const char*)(B + (size_t)(n0 + r0) * K + k0 + c * 8);
    const size_t rs = (size_t)32 * K * sizeof(__half);
    const uint32_t dstA = stage_base, dstB = stage_base + 16384;
#pragma unroll
    for (int j = 0; j < 4; j++) {
        cp_async16(dstA + soff[j], ga + (size_t)j * rs);
        cp_async16(dstB + soff[j], gb + (size_t)j * rs);
    }
    asm volatile("cp.async.commit_group;" ::: "memory");
}

// ---------------- kernel 2/4: fp16 mma.sync GEMM, 128x128 tile, 3-stage (R11 config) ----------------
template <typename CT>
__global__ void __launch_bounds__(GEMM_THREADS, 2)
k_gemm(const __half* __restrict__ A, const __half* __restrict__ B,
       CT* __restrict__ C, int K, int ldc) {
    extern __shared__ char smem[];
    const uint32_t sb = smem_u32(smem);
    const int tid = threadIdx.x, wid = tid >> 5, lane = tid & 31;
    const int m0 = blockIdx.y * BM, n0 = blockIdx.x * BN;
    const int NCH = K / BK;

    const int c = tid & 7, r0 = tid >> 3;
    uint32_t soff[4];
#pragma unroll
    for (int j = 0; j < 4; j++) {
        uint32_t o = (uint32_t)(r0 + 32 * j) * 128u + (uint32_t)c * 16u;
        soff[j] = o ^ ((o >> 3) & 0x70u);
    }

    const int warp_m = (wid >> 1) * 32, warp_n = (wid & 1) * 64;

    const uint32_t xorv = (uint32_t)(lane & 7);
    uint32_t aoff[2];
    const uint32_t adk = (uint32_t)(lane >> 4);
#pragma unroll
    for (int mt = 0; mt < 2; mt++)
        aoff[mt] = (uint32_t)(warp_m + mt * 16 + (lane & 15)) * 128u;
    uint32_t boff[4];
    const uint32_t bdk = (uint32_t)((lane >> 3) & 1);
    {
        const int br = ((lane >> 4) << 3) + (lane & 7);   // 0..15
#pragma unroll
        for (int p = 0; p < 4; p++)
            boff[p] = (uint32_t)(warp_n + p * 16 + br) * 128u;
    }

    float acc[2][8][4];
#pragma unroll
    for (int mt = 0; mt < 2; mt++)
#pragma unroll
        for (int nt = 0; nt < 8; nt++)
#pragma unroll
            for (int e = 0; e < 4; e++) acc[mt][nt][e] = 0.f;

    issue_chunk(A, B, 0, m0, n0, K, r0, c, soff, sb);
    issue_chunk(A, B, 1, m0, n0, K, r0, c, soff, sb + STAGE_BYTES);

    int stage = 0;
    int wstage = 2;
    for (int i = 0; i < NCH; i++) {
        asm volatile("cp.async.wait_group 1;" ::: "memory");
        __syncthreads();
        if (i + 2 < NCH)
            issue_chunk(A, B, i + 2, m0, n0, K, r0, c, soff,
                        sb + (uint32_t)wstage * STAGE_BYTES);
        else
            asm volatile("cp.async.commit_group;" ::: "memory");

        const uint32_t bufA = sb + (uint32_t)stage * STAGE_BYTES;
        const uint32_t bufB = bufA + 16384;
#pragma unroll
        for (int kk = 0; kk < 4; kk++) {
            const uint32_t kc = (uint32_t)kk * 2;
            uint32_t a[2][4];
#pragma unroll
            for (int mt = 0; mt < 2; mt++)
                ldsm_x4(a[mt], bufA + aoff[mt] + (((kc + adk) ^ xorv) << 4));
            uint32_t b[8][2];
#pragma unroll
            for (int p = 0; p < 4; p++) {
                uint32_t r[4];
                ldsm_x4(r, bufB + boff[p] + (((kc + bdk) ^ xorv) << 4));
                b[2 * p][0] = r[0]; b[2 * p][1] = r[1];
                b[2 * p + 1][0] = r[2]; b[2 * p + 1][1] = r[3];
            }
#pragma unroll
            for (int mt = 0; mt < 2; mt++)
#pragma unroll
                for (int nt = 0; nt < 8; nt++)
                    mma16816(acc[mt][nt], a[mt], b[nt]);
        }
        stage = (stage == 2) ? 0 : stage + 1;
        wstage = (wstage == 2) ? 0 : wstage + 1;
    }

    // epilogue: fp32 accumulators -> C (fp32 or fp16)
#pragma unroll
    for (int mt = 0; mt < 2; mt++) {
        const int row = m0 + warp_m + mt * 16 + (lane >> 2);
#pragma unroll
        for (int nt = 0; nt < 8; nt++) {
            const int col = n0 + warp_n + nt * 8 + (lane & 3) * 2;
            if constexpr (sizeof(CT) == 4) {
                float2 v0 = make_float2(acc[mt][nt][0], acc[mt][nt][1]);
                float2 v1 = make_float2(acc[mt][nt][2], acc[mt][nt][3]);
                *(float2*)((float*)C + (size_t)row * ldc + col) = v0;
                *(float2*)((float*)C + (size_t)(row + 8) * ldc + col) = v1;
            } else {
                __half2 v0 = __floats2half2_rn(acc[mt][nt][0], acc[mt][nt][1]);
                __half2 v1 = __floats2half2_rn(acc[mt][nt][2], acc[mt][nt][3]);
                *(__half2*)((__half*)C + (size_t)row * ldc + col) = v0;
                *(__half2*)((__half*)C + (size_t)(row + 8) * ldc + col) = v1;
            }
        }
    }
}

// ---------------- kernel 3: per-token (Q K^T) V via tensor cores ----------------
// 4 tokens/block (52KB smem -> 3-4 blocks/SM), 1 warp per token, warp-local pipeline.
__global__ void __launch_bounds__(MID_TPB * 32, 4) k_mid(const __half* __restrict__ qkv,
                                                         __half* __restrict__ o) {
    extern __shared__ char sm[];
    const uint32_t sb = smem_u32(sm);
    const int tid = threadIdx.x, wid = tid >> 5, lane = tid & 31;
    const int t0 = blockIdx.x * MID_TPB;

    const char* row = (const char*)(qkv + (size_t)(t0 + wid) * NQKV);
    const uint32_t tb = sb + (uint32_t)wid * MID_TOK_BYTES;

    // group 1: Q + K
#pragma unroll
    for (int i = 0; i < 16; i++) {
        const int l8 = lane + 32 * i;
        const int idx = l8 * 8;
        const int mat = idx >> 11;
        const int m = idx & 2047;
        cp_async16(tb + mat * MID_MAT_BYTES + (m >> 7) * 272 + (m & 127) * 2,
                   row + (size_t)l8 * 16);
    }
    asm volatile("cp.async.commit_group;" ::: "memory");
    // group 2: V
#pragma unroll
    for (int i = 16; i < 24; i++) {
        const int l8 = lane + 32 * i;
        const int idx = l8 * 8;
        const int m = idx & 2047;
        cp_async16(tb + 2 * MID_MAT_BYTES + (m >> 7) * 272 + (m & 127) * 2,
                   row + (size_t)l8 * 16);
    }
    asm volatile("cp.async.commit_group;" ::: "memory");

    const uint32_t qb = tb, kb = tb + MID_MAT_BYTES, vb = tb + 2 * MID_MAT_BYTES;

    asm volatile("cp.async.wait_group 1;" ::: "memory");
    __syncwarp();

    // ---- S = Q @ K^T (m16 n16 k128) ----
    float s0[4] = {0.f, 0.f, 0.f, 0.f}, s1[4] = {0.f, 0.f, 0.f, 0.f};
    const uint32_t qaddr = qb + (uint32_t)(lane & 15) * 272u + (uint32_t)(lane >> 4) * 16u;
    const uint32_t kaddr = kb + (uint32_t)(((lane >> 4) << 3) + (lane & 7)) * 272u
                              + (uint32_t)((lane >> 3) & 1) * 16u;
#pragma unroll
    for (int kk = 0; kk < 8; kk++) {
        uint32_t a[4], b[4];
        ldsm_x4(a, qaddr + kk * 32);
        ldsm_x4(b, kaddr + kk * 32);
        mma16816(s0, a, b);
        mma16816(s1, a, b + 2);
    }

    uint32_t sa[4];
    sa[0] = f2h2(s0[0], s0[1]);
    sa[1] = f2h2(s0[2], s0[3]);
    sa[2] = f2h2(s1[0], s1[1]);
    sa[3] = f2h2(s1[2], s1[3]);

    asm volatile("cp.async.wait_group 0;" ::: "memory");
    __syncwarp();

    // ---- O = S @ V (m16 n128 k16) ----
    const uint32_t vaddr = vb + (uint32_t)(lane & 15) * 272u + (uint32_t)(lane >> 4) * 16u;
    __half* op = o + (size_t)(t0 + wid) * DIM;
    const int orow = lane >> 2;
    const int colp = (lane & 3) * 2;
#pragma unroll
    for (int p = 0; p < 8; p++) {
        uint32_t v[4];
        ldsm_x4_t(v, vaddr + p * 32);
        float o0[4] = {0.f, 0.f, 0.f, 0.f}, o1[4] = {0.f, 0.f, 0.f, 0.f};
        mma16816(o0, sa, v);
        mma16816(o1, sa, v + 2);
        __half2 h00, h01, h10, h11;
        h00 = __floats2half2_rn(o0[0], o0[1]);
        h01 = __floats2half2_rn(o0[2], o0[3]);
        h10 = __floats2half2_rn(o1[0], o1[1]);
        h11 = __floats2half2_rn(o1[2], o1[3]);
        *(__half2*)(op + orow * 128 + p * 16 + colp) = h00;
        *(__half2*)(op + (orow + 8) * 128 + p * 16 + colp) = h01;
        *(__half2*)(op + orow * 128 + p * 16 + 8 + colp) = h10;
        *(__half2*)(op + (orow + 8) * 128 + p * 16 + 8 + colp) = h11;
    }
}

// ---------------- static-init preload ----------------
namespace {
struct Preload {
    Preload() {
        void* p = nullptr;
        cudaGetSymbolAddress(&p, g_x);
        cudaFuncAttributes a;
        cudaFuncGetAttributes(&a, k_prep);
        cudaFuncGetAttributes(&a, k_gemm<float>);
        cudaFuncGetAttributes(&a, k_gemm<__half>);
        cudaFuncGetAttributes(&a, k_mid);
        cudaFuncSetAttribute(k_gemm<float>, cudaFuncAttributeMaxDynamicSharedMemorySize, SMEM_BYTES);
        cudaFuncSetAttribute(k_gemm<__half>, cudaFuncAttributeMaxDynamicSharedMemorySize, SMEM_BYTES);
        cudaFuncSetAttribute(k_mid, cudaFuncAttributeMaxDynamicSharedMemorySize, MID_SMEM_BYTES);
    }
};
Preload preload_instance;
}  // namespace

// ---------------- launch ----------------
extern "C" void kernel_launch(void* const* d_in, const int* in_sizes, int n_in,
                              void* d_out, int out_size) {
    const float* x  = (const float*)d_in[0];
    const float* Wq = (const float*)d_in[1];
    const float* Wk = (const float*)d_in[2];
    const float* Wv = (const float*)d_in[3];
    const float* Wo = (const float*)d_in[4];
    float* out = (float*)d_out;

    __half *xh, *wqkv, *wo, *qkv, *oh;
    cudaGetSymbolAddress((void**)&xh,   g_x);
    cudaGetSymbolAddress((void**)&wqkv, g_wqkv);
    cudaGetSymbolAddress((void**)&wo,   g_wo);
    cudaGetSymbolAddress((void**)&qkv,  g_qkv);
    cudaGetSymbolAddress((void**)&oh,   g_o);

    cudaFuncSetAttribute(k_gemm<float>, cudaFuncAttributeMaxDynamicSharedMemorySize, SMEM_BYTES);
    cudaFuncSetAttribute(k_gemm<__half>, cudaFuncAttributeMaxDynamicSharedMemorySize, SMEM_BYTES);
    cudaFuncSetAttribute(k_mid, cudaFuncAttributeMaxDynamicSharedMemorySize, MID_SMEM_BYTES);

    // 1) fused prep: weight transpose+round (z<4) and x convert (z=4), one launch
    k_prep<<<dim3(64, 64, 5), dim3(32, 8)>>>(x, Wq, Wk, Wv, Wo, xh, wqkv, wo);
    // 2) QKV = x @ [Wq|Wk|Wv]   (fp16 in, fp16 out)
    k_gemm<__half><<<dim3(NQKV / BN, TOK / BM), GEMM_THREADS, SMEM_BYTES>>>(
        xh, wqkv, qkv, DIM, NQKV);
    // 3) per-token (QK^T)V via tensor cores, 4 tokens/block, warp-local pipeline
    k_mid<<<TOK / MID_TPB, MID_TPB * 32, MID_SMEM_BYTES>>>(qkv, oh);
    // 4) out = o @ Wo  (fp32 out)
    k_gemm<float><<<dim3(DIM / BN, TOK / BM), GEMM_THREADS, SMEM_BYTES>>>(
        oh, wo, out, DIM, DIM);
}